// round 7
// baseline (speedup 1.0000x reference)
#include <cuda_runtime.h>
#include <cuda_bf16.h>
#include <cstddef>

// CompressK: ragged strided chunk mean-pool (NSA K compression).
//   k:          [total_tokens, H, D] fp32   (H*D = 512 here)
//   cu_seqlens: [B+1] int32
//   kernel_size, kernel_stride: int32 scalars (device)
// Output: compressed_k [NC, H, D] fp32 followed by (B+1) compressed
// cu_seqlens as float values.
//
// R6: G=4 chunk groups (5 shared halves -> 1.25 halves/chunk of traffic)
// with 512-thread blocks: a 4-way "sub" dimension parallelizes each
// half-sum (4 rows/thread), restoring warp supply (~16 warps/CTA, 515
// CTAs). Cross-sub combine via smem; final reduce is exactly 4 chunks x
// 128 lanes = 512 outputs, one per thread.

#define HD    512          // H * D
#define HD4   (HD / 4)     // float4 lanes per row
#define G     4            // chunks per block (fast path)
#define NSUB  4            // parallel splits of each half-sum
#define BLK   (HD4 * NSUB) // 512 threads
#define KS_C  32
#define ST_C  16
#define RPS   (ST_C / NSUB)  // rows per thread per half = 4

__global__ void __launch_bounds__(BLK, 3)
compressk_kernel(const float4* __restrict__ k4,
                 const int*    __restrict__ cu,
                 const int*    __restrict__ p_ks,
                 const int*    __restrict__ p_st,
                 float4*       __restrict__ out4,
                 float*        __restrict__ out_tail,
                 int B, int tail_n)
{
    __shared__ float4 buf[NSUB][G][HD4];   // 32 KB

    const int tid  = threadIdx.x;
    const int lane = tid & (HD4 - 1);
    const int sub  = tid >> 7;             // 0..NSUB-1
    const int g    = blockIdx.x;
    const int ks   = __ldg(p_ks);
    const int st   = __ldg(p_st);

    // Fused tail: block 0 writes compressed cu_seqlens.
    if (g == 0 && tid < tail_n) {
        int acc = 0;
        for (int j = 0; j < tid; j++) {
            const int len = __ldg(cu + j + 1) - __ldg(cu + j);
            acc += (len >= ks) ? (len - ks) / st + 1 : 0;
        }
        out_tail[tid] = (float)acc;
    }

    // Locate this block's chunk group via a scan over (tiny) cu_seqlens.
    int start_tok = 0, chunk0 = 0, gn = 0;
    {
        int gacc = 0, cacc = 0;
        #pragma unroll 4
        for (int i = 0; i < B; i++) {
            const int s0  = __ldg(cu + i);
            const int s1  = __ldg(cu + i + 1);
            const int len = s1 - s0;
            const int nc  = (len >= ks) ? (len - ks) / st + 1 : 0;
            const int ng  = (nc + G - 1) / G;
            if (g >= gacc && g < gacc + ng) {
                const int gi = g - gacc;
                const int c0 = gi * G;
                gn        = min(G, nc - c0);
                chunk0    = cacc + c0;
                start_tok = s0 + c0 * st;
            }
            gacc += ng;
            cacc += nc;
        }
    }
    if (gn <= 0) return;

    const float inv = 1.0f / (float)ks;

    if (ks == KS_C && st == ST_C) {
        // ── Fast path ───────────────────────────────────────────────────
        // Half h covers rows [start_tok + h*ST_C, +ST_C). This thread sums
        // rows sub*RPS .. sub*RPS+RPS-1 of each needed half (h <= gn).
        float4 part[G + 1];
        const float4* base =
            k4 + (size_t)(start_tok + sub * RPS) * HD4 + lane;

        #pragma unroll
        for (int h = 0; h <= G; h++) {
            float4 s = make_float4(0.f, 0.f, 0.f, 0.f);
            if (h <= gn) {
                const float4* p = base + (size_t)h * ST_C * HD4;
                float4 v[RPS];
                #pragma unroll
                for (int r = 0; r < RPS; r++) v[r] = p[(size_t)r * HD4];
                #pragma unroll
                for (int r = 0; r < RPS; r++) {
                    s.x += v[r].x; s.y += v[r].y;
                    s.z += v[r].z; s.w += v[r].w;
                }
            }
            part[h] = s;
        }

        // Per-chunk partial (this sub's share): chunk c = half c + half c+1.
        #pragma unroll
        for (int c = 0; c < G; c++) {
            float4 pc;
            pc.x = part[c].x + part[c + 1].x;
            pc.y = part[c].y + part[c + 1].y;
            pc.z = part[c].z + part[c + 1].z;
            pc.w = part[c].w + part[c + 1].w;
            buf[sub][c][lane] = pc;
        }
        __syncthreads();

        // Final reduce: thread (sub=c, lane) owns output chunk c, lane.
        const int c = sub;
        if (c < gn) {
            float4 s = buf[0][c][lane];
            #pragma unroll
            for (int u = 1; u < NSUB; u++) {
                const float4 v = buf[u][c][lane];
                s.x += v.x; s.y += v.y; s.z += v.z; s.w += v.w;
            }
            s.x *= inv; s.y *= inv; s.z *= inv; s.w *= inv;
            out4[(size_t)(chunk0 + c) * HD4 + lane] = s;
        }
    } else {
        // ── Generic fallback: sub c computes chunk c naively ────────────
        const int c = sub;
        if (c < gn) {
            const float4* p =
                k4 + (size_t)(start_tok + c * st) * HD4 + lane;
            float4 s = make_float4(0.f, 0.f, 0.f, 0.f);
            for (int t = 0; t < ks; t++) {
                const float4 v = p[(size_t)t * HD4];
                s.x += v.x; s.y += v.y; s.z += v.z; s.w += v.w;
            }
            s.x *= inv; s.y *= inv; s.z *= inv; s.w *= inv;
            out4[(size_t)(chunk0 + c) * HD4 + lane] = s;
        }
    }
}

extern "C" void kernel_launch(void* const* d_in, const int* in_sizes, int n_in,
                              void* d_out, int out_size)
{
    const float4* k4   = (const float4*)d_in[0];
    const int*    cu   = (const int*)d_in[1];
    const int*    p_ks = (const int*)d_in[2];
    const int*    p_st = (const int*)d_in[3];

    const int B = in_sizes[1] - 1;

    const int NC   = out_size / HD;
    const int tail = out_size - NC * HD;
    if (NC <= 0) return;

    // Upper bound on groups: ceil(NC/G) plus one partial group per sequence.
    const int max_groups = (NC + G - 1) / G + B;

    compressk_kernel<<<max_groups, BLK>>>(
        k4, cu, p_ks, p_st,
        (float4*)d_out,
        (float*)d_out + (size_t)NC * HD,
        B, tail);
}

// round 8
// speedup vs baseline: 1.0025x; 1.0025x over previous
#include <cuda_runtime.h>
#include <cuda_bf16.h>
#include <cstddef>

// CompressK: ragged strided chunk mean-pool (NSA K compression).
//   k:          [total_tokens, H, D] fp32   (H*D = 512 here)
//   cu_seqlens: [B+1] int32
//   kernel_size, kernel_stride: int32 scalars (device)
// Output: compressed_k [NC, H, D] fp32 followed by (B+1) compressed
// cu_seqlens as float values.
//
// R7: G=2 chunk groups (3 shared halves -> 1.5 halves/chunk traffic) with
// 256-thread blocks: NSUB=2 splits each 16-row half-sum across two thread
// groups (8 rows/thread), doubling warp supply vs R4 at the same grid
// size. All fast-path loads are UNCONDITIONAL (partial-group halves are
// address-clamped, results masked at the write), so ptxas can pipeline
// the full 24-load stream. Cross-sub combine via 8KB smem; final reduce
// maps 2 subs x 2 chunks onto all 256 threads (one output each).

#define HD    512            // H * D
#define HD4   (HD / 4)       // float4 lanes per row
#define G     2              // chunks per block (fast path)
#define NSUB  2              // parallel splits of each half-sum
#define BLK   (HD4 * NSUB)   // 256 threads
#define KS_C  32
#define ST_C  16
#define RPS   (ST_C / NSUB)  // rows per thread per half = 8

__global__ void __launch_bounds__(BLK)
compressk_kernel(const float4* __restrict__ k4,
                 const int*    __restrict__ cu,
                 const int*    __restrict__ p_ks,
                 const int*    __restrict__ p_st,
                 float4*       __restrict__ out4,
                 float*        __restrict__ out_tail,
                 int B, int tail_n)
{
    __shared__ float4 buf[NSUB][G][HD4];   // 8 KB

    const int tid  = threadIdx.x;
    const int lane = tid & (HD4 - 1);
    const int sub  = tid >> 7;             // 0..NSUB-1
    const int g    = blockIdx.x;
    const int ks   = __ldg(p_ks);
    const int st   = __ldg(p_st);
    const int T    = __ldg(cu + B);        // total tokens

    // Fused tail: block 0 writes compressed cu_seqlens.
    if (g == 0 && tid < tail_n) {
        int acc = 0;
        for (int j = 0; j < tid; j++) {
            const int len = __ldg(cu + j + 1) - __ldg(cu + j);
            acc += (len >= ks) ? (len - ks) / st + 1 : 0;
        }
        out_tail[tid] = (float)acc;
    }

    // Locate this block's chunk group via a scan over (tiny) cu_seqlens.
    int start_tok = 0, chunk0 = 0, gn = 0;
    {
        int gacc = 0, cacc = 0;
        #pragma unroll 4
        for (int i = 0; i < B; i++) {
            const int s0  = __ldg(cu + i);
            const int s1  = __ldg(cu + i + 1);
            const int len = s1 - s0;
            const int nc  = (len >= ks) ? (len - ks) / st + 1 : 0;
            const int ng  = (nc + G - 1) / G;
            if (g >= gacc && g < gacc + ng) {
                const int gi = g - gacc;
                const int c0 = gi * G;
                gn        = min(G, nc - c0);
                chunk0    = cacc + c0;
                start_tok = s0 + c0 * st;
            }
            gacc += ng;
            cacc += nc;
        }
    }
    if (gn <= 0) return;

    const float inv = 1.0f / (float)ks;

    if (ks == KS_C && st == ST_C) {
        // ── Fast path ───────────────────────────────────────────────────
        // Half h covers rows [start_tok + h*ST_C, +ST_C); this thread sums
        // its RPS-row slice of halves 0..G. Loads are unconditional: for
        // partial groups the unused trailing half is clamped in-bounds
        // (its garbage sum is never combined into a written chunk).
        float4 part[G + 1];

        #pragma unroll
        for (int h = 0; h <= G; h++) {
            int row0 = start_tok + h * ST_C;
            row0 = min(row0, T - ST_C);          // clamp whole half in-bounds
            const float4* p =
                k4 + (size_t)(row0 + sub * RPS) * HD4 + lane;

            float4 v[RPS];
            #pragma unroll
            for (int r = 0; r < RPS; r++) v[r] = p[(size_t)r * HD4];

            float4 s = make_float4(0.f, 0.f, 0.f, 0.f);
            #pragma unroll
            for (int r = 0; r < RPS; r++) {
                s.x += v[r].x; s.y += v[r].y;
                s.z += v[r].z; s.w += v[r].w;
            }
            part[h] = s;
        }

        // Per-chunk partial: chunk c = half c + half c+1 (this sub's share).
        #pragma unroll
        for (int c = 0; c < G; c++) {
            float4 pc;
            pc.x = part[c].x + part[c + 1].x;
            pc.y = part[c].y + part[c + 1].y;
            pc.z = part[c].z + part[c + 1].z;
            pc.w = part[c].w + part[c + 1].w;
            buf[sub][c][lane] = pc;
        }
        __syncthreads();

        // Final reduce: thread (sub=c, lane) owns output (chunk0+c, lane).
        const int c = sub;
        if (c < gn) {
            float4 s = buf[0][c][lane];
            #pragma unroll
            for (int u = 1; u < NSUB; u++) {
                const float4 v = buf[u][c][lane];
                s.x += v.x; s.y += v.y; s.z += v.z; s.w += v.w;
            }
            s.x *= inv; s.y *= inv; s.z *= inv; s.w *= inv;
            out4[(size_t)(chunk0 + c) * HD4 + lane] = s;
        }
    } else {
        // ── Generic fallback: sub c computes chunk c naively ────────────
        const int c = sub;
        if (c < gn) {
            const float4* p =
                k4 + (size_t)(start_tok + c * st) * HD4 + lane;
            float4 s = make_float4(0.f, 0.f, 0.f, 0.f);
            for (int t = 0; t < ks; t++) {
                const float4 v = p[(size_t)t * HD4];
                s.x += v.x; s.y += v.y; s.z += v.z; s.w += v.w;
            }
            s.x *= inv; s.y *= inv; s.z *= inv; s.w *= inv;
            out4[(size_t)(chunk0 + c) * HD4 + lane] = s;
        }
    }
}

extern "C" void kernel_launch(void* const* d_in, const int* in_sizes, int n_in,
                              void* d_out, int out_size)
{
    const float4* k4   = (const float4*)d_in[0];
    const int*    cu   = (const int*)d_in[1];
    const int*    p_ks = (const int*)d_in[2];
    const int*    p_st = (const int*)d_in[3];

    const int B = in_sizes[1] - 1;

    const int NC   = out_size / HD;
    const int tail = out_size - NC * HD;
    if (NC <= 0) return;

    // Upper bound on groups: ceil(NC/G) plus one partial group per sequence.
    const int max_groups = (NC + G - 1) / G + B;

    compressk_kernel<<<max_groups, BLK>>>(
        k4, cu, p_ks, p_st,
        (float4*)d_out,
        (float*)d_out + (size_t)NC * HD,
        B, tail);
}